// round 1
// baseline (speedup 1.0000x reference)
#include <cuda_runtime.h>
#include <cuda_bf16.h>
#include <math.h>

// Problem constants (fixed by reference): values [256, 262144] fp32.
#define B 256
#define N 262144
#define VEC4_PER_ROW (N / 4)          // 65536 float4 per row
#define BLOCKS_PER_ROW 16
#define THREADS 256
#define THREADS_PER_ROW (BLOCKS_PER_ROW * THREADS)   // 4096
#define VEC4_PER_THREAD (VEC4_PER_ROW / THREADS_PER_ROW) // 16

__device__ unsigned int g_counts[B];

__global__ void zero_counts_kernel() {
    g_counts[threadIdx.x] = 0u;
}

__global__ void __launch_bounds__(THREADS) count_kernel(const float* __restrict__ vals) {
    const int row = blockIdx.y;
    const float4* __restrict__ p =
        reinterpret_cast<const float4*>(vals) + (size_t)row * VEC4_PER_ROW;

    const int base = blockIdx.x * THREADS + threadIdx.x;

    int cnt = 0;
#pragma unroll
    for (int k = 0; k < VEC4_PER_THREAD; ++k) {
        float4 v = p[base + k * THREADS_PER_ROW];
        cnt += (v.x > 0.0f);
        cnt += (v.y > 0.0f);
        cnt += (v.z > 0.0f);
        cnt += (v.w > 0.0f);
    }

    // warp reduce
#pragma unroll
    for (int o = 16; o > 0; o >>= 1)
        cnt += __shfl_xor_sync(0xFFFFFFFFu, cnt, o);

    if ((threadIdx.x & 31) == 0)
        atomicAdd(&g_counts[row], (unsigned)cnt);
}

__global__ void entropy_kernel(float* __restrict__ out) {
    const int r = threadIdx.x;
    const float n = (float)N;
    const float c1 = (float)g_counts[r];
    const float c0 = n - c1;
    const float denom = n + 1e-8f;
    const float p0 = c0 / denom;
    const float p1 = c1 / denom;
    float t0 = (p0 > 0.0f) ? p0 * log2f(p0 + 1e-10f) : 0.0f;
    float t1 = (p1 > 0.0f) ? p1 * log2f(p1 + 1e-10f) : 0.0f;
    out[r] = -(t0 + t1);
}

extern "C" void kernel_launch(void* const* d_in, const int* in_sizes, int n_in,
                              void* d_out, int out_size) {
    const float* vals = (const float*)d_in[0];
    float* out = (float*)d_out;

    zero_counts_kernel<<<1, B>>>();
    dim3 grid(BLOCKS_PER_ROW, B);
    count_kernel<<<grid, THREADS>>>(vals);
    entropy_kernel<<<1, B>>>(out);
}

// round 2
// speedup vs baseline: 1.0894x; 1.0894x over previous
#include <cuda_runtime.h>
#include <cuda_bf16.h>
#include <math.h>

// Problem constants (fixed by reference): values [256, 262144] fp32.
#define B 256
#define N 262144
#define VEC4_PER_ROW (N / 4)          // 65536 float4 per row
#define BLOCKS_PER_ROW 16
#define THREADS 256
#define THREADS_PER_ROW (BLOCKS_PER_ROW * THREADS)        // 4096
#define VEC4_PER_THREAD (VEC4_PER_ROW / THREADS_PER_ROW)  // 16

// Deterministic scratch: every slot is written on every launch -> no zeroing.
__device__ unsigned int g_partials[B * BLOCKS_PER_ROW];

__global__ void __launch_bounds__(THREADS) count_kernel(const float* __restrict__ vals) {
    const int row = blockIdx.y;
    const int blk = blockIdx.x;
    const float4* __restrict__ p =
        reinterpret_cast<const float4*>(vals) + (size_t)row * VEC4_PER_ROW;

    const int base = blk * THREADS + threadIdx.x;

    int cnt = 0;
#pragma unroll
    for (int k = 0; k < VEC4_PER_THREAD; ++k) {
        float4 v = __ldcs(&p[base + k * THREADS_PER_ROW]);  // read-once: evict-first
        cnt += (v.x > 0.0f);
        cnt += (v.y > 0.0f);
        cnt += (v.z > 0.0f);
        cnt += (v.w > 0.0f);
    }

    // warp reduce
#pragma unroll
    for (int o = 16; o > 0; o >>= 1)
        cnt += __shfl_xor_sync(0xFFFFFFFFu, cnt, o);

    // block reduce via smem (8 warps)
    __shared__ int warp_sums[THREADS / 32];
    if ((threadIdx.x & 31) == 0)
        warp_sums[threadIdx.x >> 5] = cnt;
    __syncthreads();

    if (threadIdx.x == 0) {
        int s = 0;
#pragma unroll
        for (int w = 0; w < THREADS / 32; ++w) s += warp_sums[w];
        g_partials[row * BLOCKS_PER_ROW + blk] = (unsigned)s;
    }
}

__global__ void entropy_kernel(float* __restrict__ out) {
    const int r = threadIdx.x;

    unsigned c = 0;
#pragma unroll
    for (int i = 0; i < BLOCKS_PER_ROW; ++i)
        c += g_partials[r * BLOCKS_PER_ROW + i];

    const float n = (float)N;
    const float c1 = (float)c;
    const float c0 = n - c1;
    const float denom = n + 1e-8f;
    const float p0 = c0 / denom;
    const float p1 = c1 / denom;
    float t0 = (p0 > 0.0f) ? p0 * log2f(p0 + 1e-10f) : 0.0f;
    float t1 = (p1 > 0.0f) ? p1 * log2f(p1 + 1e-10f) : 0.0f;
    out[r] = -(t0 + t1);
}

extern "C" void kernel_launch(void* const* d_in, const int* in_sizes, int n_in,
                              void* d_out, int out_size) {
    const float* vals = (const float*)d_in[0];
    float* out = (float*)d_out;

    dim3 grid(BLOCKS_PER_ROW, B);
    count_kernel<<<grid, THREADS>>>(vals);
    entropy_kernel<<<1, B>>>(out);
}

// round 3
// speedup vs baseline: 1.0901x; 1.0007x over previous
#include <cuda_runtime.h>
#include <cuda_bf16.h>
#include <math.h>

// Problem constants (fixed by reference): values [256, 262144] fp32.
#define B 256
#define N 262144
#define VEC4_PER_ROW (N / 4)          // 65536 float4 per row
#define BLOCKS_PER_ROW 16
#define THREADS 256
#define THREADS_PER_ROW (BLOCKS_PER_ROW * THREADS)        // 4096
#define VEC4_PER_THREAD (VEC4_PER_ROW / THREADS_PER_ROW)  // 16
#define TOTAL_BLOCKS (B * BLOCKS_PER_ROW)                 // 4096

// Deterministic scratch: every partial slot is written on every launch.
// g_ticket is reset to 0 by the last block each launch -> graph-replay safe.
__device__ unsigned int g_partials[B * BLOCKS_PER_ROW];
__device__ unsigned int g_ticket;   // zero-initialized at module load; self-resetting after

__global__ void __launch_bounds__(THREADS) fused_entropy_kernel(
    const float* __restrict__ vals, float* __restrict__ out) {
    const int row = blockIdx.y;
    const int blk = blockIdx.x;
    const float4* __restrict__ p =
        reinterpret_cast<const float4*>(vals) + (size_t)row * VEC4_PER_ROW;

    const int base = blk * THREADS + threadIdx.x;

    int cnt = 0;
#pragma unroll
    for (int k = 0; k < VEC4_PER_THREAD; ++k) {
        float4 v = __ldcs(&p[base + k * THREADS_PER_ROW]);  // read-once: evict-first
        cnt += (v.x > 0.0f);
        cnt += (v.y > 0.0f);
        cnt += (v.z > 0.0f);
        cnt += (v.w > 0.0f);
    }

    // warp reduce
#pragma unroll
    for (int o = 16; o > 0; o >>= 1)
        cnt += __shfl_xor_sync(0xFFFFFFFFu, cnt, o);

    // block reduce via smem (8 warps)
    __shared__ int warp_sums[THREADS / 32];
    __shared__ bool s_is_last;
    if ((threadIdx.x & 31) == 0)
        warp_sums[threadIdx.x >> 5] = cnt;
    __syncthreads();

    if (threadIdx.x == 0) {
        int s = 0;
#pragma unroll
        for (int w = 0; w < THREADS / 32; ++w) s += warp_sums[w];
        g_partials[row * BLOCKS_PER_ROW + blk] = (unsigned)s;
        __threadfence();  // publish partial before taking a ticket
        unsigned t = atomicAdd(&g_ticket, 1u);
        s_is_last = (t == TOTAL_BLOCKS - 1);
    }
    __syncthreads();

    if (!s_is_last) return;

    // ---- Last block: epilogue. One thread per batch row. ----
    {
        const int r = threadIdx.x;  // THREADS == B == 256
        unsigned c = 0;
#pragma unroll
        for (int i = 0; i < BLOCKS_PER_ROW; ++i)
            c += g_partials[r * BLOCKS_PER_ROW + i];

        const float n = (float)N;
        const float c1 = (float)c;
        const float c0 = n - c1;
        const float denom = n + 1e-8f;
        const float p0 = c0 / denom;
        const float p1 = c1 / denom;
        float t0 = (p0 > 0.0f) ? p0 * log2f(p0 + 1e-10f) : 0.0f;
        float t1 = (p1 > 0.0f) ? p1 * log2f(p1 + 1e-10f) : 0.0f;
        out[r] = -(t0 + t1);

        if (r == 0) g_ticket = 0u;  // reset for next graph replay (deterministic)
    }
}

extern "C" void kernel_launch(void* const* d_in, const int* in_sizes, int n_in,
                              void* d_out, int out_size) {
    const float* vals = (const float*)d_in[0];
    float* out = (float*)d_out;

    dim3 grid(BLOCKS_PER_ROW, B);
    fused_entropy_kernel<<<grid, THREADS>>>(vals, out);
}